// round 6
// baseline (speedup 1.0000x reference)
#include <cuda_runtime.h>

// MLP_89498528514757 — fused recommender MLP, fp32. Round 6:
// grid 256 x 512 threads, 2 blocks/SM. Vectorized-j GEMM layers:
// each thread owns 4 consecutive j columns -> layer 2 iter =
// LDG.128 (4 weights) + LDS.128 (h1, 4 rows) + 16 FFMA.
// Split-K partials in one 32KB smem union, flat conflict-free combines.

#define NUM_USERS 100000
#define BATCH     1024
#define ROWS      4

__global__ __launch_bounds__(512, 2)
void mlp_fused_kernel(const int*   __restrict__ user_ids,
                      const int*   __restrict__ item_ids,
                      const float* __restrict__ W1, const float* __restrict__ b1,
                      const float* __restrict__ W2, const float* __restrict__ b2,
                      const float* __restrict__ W3, const float* __restrict__ b3,
                      const float* __restrict__ W4, const float* __restrict__ b4,
                      float*       __restrict__ out)
{
    __shared__ float4 h1t[256];                  // [k] -> 4 rows      (4 KB)
    __shared__ union {
        float4 l2[16][128];                      // [kq][j] -> rows   (32 KB)
        float4 l3[32][64];                       // [ks][j] -> rows   (32 KB)
    } P;
    __shared__ float4 h2t[128];                  // [k] -> rows        (2 KB)
    __shared__ float4 h3t[64];                   // [j] -> rows        (1 KB)

    const int t    = threadIdx.x;                // 0..511
    const int row0 = blockIdx.x * ROWS;

    // ---------------- Layer 1: dependent DRAM gather chain FIRST -----------
    const int k1 = t & 255;
    const int g  = t >> 8;                       // 0/1 -> rows {2g,2g+1}
    const int ra = row0 + g * 2;
    const int ua = user_ids[ra],     ia = item_ids[ra];
    const int ub = user_ids[ra + 1], ib = item_ids[ra + 1];
    const float gva = W1[ua * 256 + k1], eva = W1[(NUM_USERS + ia) * 256 + k1];
    const float gvb = W1[ub * 256 + k1], evb = W1[(NUM_USERS + ib) * 256 + k1];

    // ---- overlap while gather is in flight: indices, biases, W2 prefetch --
    const int jg2 = (t & 31) * 4;                // layer-2 j base (4 cols)
    const int kq  = t >> 5;                      // 0..15 k-split (16 iters)
    const float4* __restrict__ w2p =
        reinterpret_cast<const float4*>(W2 + (kq * 16) * 128 + jg2);
    float4 w2pre[4];
    #pragma unroll
    for (int i = 0; i < 4; ++i) w2pre[i] = w2p[i * 32];   // 32 float4 per k-row

    const float bj2 = b2[t >> 2];                // combine2: j = t>>2
    const float bj3 = b3[(t >> 2) & 63];         // combine3: j = t>>2 (t<256)
    float w4a = 0.f, w4b = 0.f, bb4 = 0.f;
    if (t < 32) { w4a = W4[t]; w4b = W4[t + 32]; bb4 = b4[0]; }

    // finish layer 1 (thread writes 2 rows of h1t[k1])
    {
        const float bk = b1[k1];
        float2 h;
        h.x = fmaxf(gva + eva + bk, 0.f);
        h.y = fmaxf(gvb + evb + bk, 0.f);
        *reinterpret_cast<float2*>(
            reinterpret_cast<float*>(&h1t[k1]) + g * 2) = h;
    }
    __syncthreads();

    // ---------------- Layer 2: [4x256] @ W2[256x128], 16-way K, 4 j/thread -
    {
        float4 a0 = make_float4(0.f,0.f,0.f,0.f);
        float4 a1 = a0, a2 = a0, a3 = a0;
        #pragma unroll
        for (int kk = 0; kk < 4; ++kk) {         // prefetched weights
            const float4 w = w2pre[kk];
            const float4 v = h1t[kq * 16 + kk];  // warp-broadcast LDS.128
            a0.x = fmaf(v.x, w.x, a0.x); a0.y = fmaf(v.y, w.x, a0.y);
            a0.z = fmaf(v.z, w.x, a0.z); a0.w = fmaf(v.w, w.x, a0.w);
            a1.x = fmaf(v.x, w.y, a1.x); a1.y = fmaf(v.y, w.y, a1.y);
            a1.z = fmaf(v.z, w.y, a1.z); a1.w = fmaf(v.w, w.y, a1.w);
            a2.x = fmaf(v.x, w.z, a2.x); a2.y = fmaf(v.y, w.z, a2.y);
            a2.z = fmaf(v.z, w.z, a2.z); a2.w = fmaf(v.w, w.z, a2.w);
            a3.x = fmaf(v.x, w.w, a3.x); a3.y = fmaf(v.y, w.w, a3.y);
            a3.z = fmaf(v.z, w.w, a3.z); a3.w = fmaf(v.w, w.w, a3.w);
        }
        #pragma unroll
        for (int kk = 4; kk < 16; ++kk) {
            const float4 w = w2p[kk * 32];       // LDG.128, coalesced
            const float4 v = h1t[kq * 16 + kk];
            a0.x = fmaf(v.x, w.x, a0.x); a0.y = fmaf(v.y, w.x, a0.y);
            a0.z = fmaf(v.z, w.x, a0.z); a0.w = fmaf(v.w, w.x, a0.w);
            a1.x = fmaf(v.x, w.y, a1.x); a1.y = fmaf(v.y, w.y, a1.y);
            a1.z = fmaf(v.z, w.y, a1.z); a1.w = fmaf(v.w, w.y, a1.w);
            a2.x = fmaf(v.x, w.z, a2.x); a2.y = fmaf(v.y, w.z, a2.y);
            a2.z = fmaf(v.z, w.z, a2.z); a2.w = fmaf(v.w, w.z, a2.w);
            a3.x = fmaf(v.x, w.w, a3.x); a3.y = fmaf(v.y, w.w, a3.y);
            a3.z = fmaf(v.z, w.w, a3.z); a3.w = fmaf(v.w, w.w, a3.w);
        }
        P.l2[kq][jg2 + 0] = a0;                  // conflict-free STS.128
        P.l2[kq][jg2 + 1] = a1;
        P.l2[kq][jg2 + 2] = a2;
        P.l2[kq][jg2 + 3] = a3;
    }

    // ---- layer-3 weight prefetch (accumulators dead; before the sync) ----
    const int jg3 = (t & 15) * 4;                // layer-3 j base (4 cols)
    const int ks3 = t >> 4;                      // 0..31 k-split (4 iters)
    const float4* __restrict__ w3p =
        reinterpret_cast<const float4*>(W3 + (ks3 * 4) * 64 + jg3);
    float4 w3pre[4];
    #pragma unroll
    for (int i = 0; i < 4; ++i) w3pre[i] = w3p[i * 16];   // 16 float4 per k-row
    __syncthreads();

    // combine layer-2 partials: 512 threads, element (j = t>>2, r = t&3)
    {
        const int j = t >> 2, r = t & 3;
        float s = bj2;
        #pragma unroll
        for (int q = 0; q < 16; ++q)
            s += reinterpret_cast<const float*>(&P.l2[q][j])[r];
        reinterpret_cast<float*>(&h2t[j])[r] = fmaxf(s, 0.f);
    }
    __syncthreads();

    // ---------------- Layer 3: [4x128] @ W3[128x64], 32-way K, 4 j/thread --
    {
        float4 c0 = make_float4(0.f,0.f,0.f,0.f);
        float4 c1 = c0, c2 = c0, c3 = c0;
        #pragma unroll
        for (int kk = 0; kk < 4; ++kk) {
            const float4 w = w3pre[kk];
            const float4 v = h2t[ks3 * 4 + kk];
            c0.x = fmaf(v.x, w.x, c0.x); c0.y = fmaf(v.y, w.x, c0.y);
            c0.z = fmaf(v.z, w.x, c0.z); c0.w = fmaf(v.w, w.x, c0.w);
            c1.x = fmaf(v.x, w.y, c1.x); c1.y = fmaf(v.y, w.y, c1.y);
            c1.z = fmaf(v.z, w.y, c1.z); c1.w = fmaf(v.w, w.y, c1.w);
            c2.x = fmaf(v.x, w.z, c2.x); c2.y = fmaf(v.y, w.z, c2.y);
            c2.z = fmaf(v.z, w.z, c2.z); c2.w = fmaf(v.w, w.z, c2.w);
            c3.x = fmaf(v.x, w.w, c3.x); c3.y = fmaf(v.y, w.w, c3.y);
            c3.z = fmaf(v.z, w.w, c3.z); c3.w = fmaf(v.w, w.w, c3.w);
        }
        P.l3[ks3][jg3 + 0] = c0;
        P.l3[ks3][jg3 + 1] = c1;
        P.l3[ks3][jg3 + 2] = c2;
        P.l3[ks3][jg3 + 3] = c3;
    }
    __syncthreads();

    // combine layer-3 partials: 256 threads, element (j = t>>2, r = t&3)
    if (t < 256) {
        const int j = t >> 2, r = t & 3;
        float s = bj3;
        #pragma unroll
        for (int q = 0; q < 32; ++q)
            s += reinterpret_cast<const float*>(&P.l3[q][j])[r];
        reinterpret_cast<float*>(&h3t[j])[r] = fmaxf(s, 0.f);
    }
    __syncthreads();

    // ---------------- Layer 4: [4x64] @ W4[64x1] + b4 (warp 0) -------------
    if (t < 32) {
        const float4 va = h3t[t], vb = h3t[t + 32];
        float a0 = fmaf(va.x, w4a, vb.x * w4b);
        float a1 = fmaf(va.y, w4a, vb.y * w4b);
        float a2 = fmaf(va.z, w4a, vb.z * w4b);
        float a3 = fmaf(va.w, w4a, vb.w * w4b);
        #pragma unroll
        for (int off = 16; off > 0; off >>= 1) {
            a0 += __shfl_down_sync(0xffffffffu, a0, off);
            a1 += __shfl_down_sync(0xffffffffu, a1, off);
            a2 += __shfl_down_sync(0xffffffffu, a2, off);
            a3 += __shfl_down_sync(0xffffffffu, a3, off);
        }
        if (t == 0) {
            out[row0 + 0] = a0 + bb4;
            out[row0 + 1] = a1 + bb4;
            out[row0 + 2] = a2 + bb4;
            out[row0 + 3] = a3 + bb4;
        }
    }
}

extern "C" void kernel_launch(void* const* d_in, const int* in_sizes, int n_in,
                              void* d_out, int out_size)
{
    const int*   user_ids = (const int*)  d_in[0];
    const int*   item_ids = (const int*)  d_in[1];
    const float* W1       = (const float*)d_in[2];
    const float* b1       = (const float*)d_in[3];
    const float* W2       = (const float*)d_in[4];
    const float* b2       = (const float*)d_in[5];
    const float* W3       = (const float*)d_in[6];
    const float* b3       = (const float*)d_in[7];
    const float* W4       = (const float*)d_in[8];
    const float* b4       = (const float*)d_in[9];
    float*       out      = (float*)d_out;

    mlp_fused_kernel<<<BATCH / ROWS, 512>>>(user_ids, item_ids,
                                            W1, b1, W2, b2, W3, b3, W4, b4, out);
}